// round 2
// baseline (speedup 1.0000x reference)
#include <cuda_runtime.h>
#include <math.h>

#define N_NODES 50000
#define N_EDGES 800000
#define F_IN    500
#define F_HID   128
#define F_OUT   47
#define F_PAD   48

// ---------------- scratch (static device allocations only) ----------------
__device__ float g_H1  [(size_t)N_NODES * F_HID];   // X@W1
__device__ float g_AGG1[(size_t)N_NODES * F_HID];   // aggregated layer1
__device__ float g_H2  [(size_t)N_NODES * F_PAD];   // relu(A1+b1)@W2 (padded)
__device__ float g_AGG2[(size_t)N_NODES * F_PAD];   // aggregated layer2
__device__ int   g_deg [N_NODES];
__device__ float g_dinv[N_NODES];
__device__ int   g_src [N_EDGES];
__device__ int   g_dst [N_EDGES];
__device__ int   g_is64;

// ---------------- edge dtype detect + convert ----------------
// If edge_index is int64 (values < 50000), every odd 32-bit word is 0.
// If int32, odd words are uniform in [0, 50000) -> essentially never all zero.
__global__ void k_detect(const unsigned int* __restrict__ w) {
    __shared__ int nz;
    if (threadIdx.x == 0) nz = 0;
    __syncthreads();
    unsigned int v = w[2 * threadIdx.x + 1];   // first 128 odd words (well within buffer)
    if (v != 0u) atomicAdd(&nz, 1);
    __syncthreads();
    if (threadIdx.x == 0) g_is64 = (nz == 0) ? 1 : 0;
}

__global__ void k_convert(const unsigned int* __restrict__ w) {
    int e = blockIdx.x * blockDim.x + threadIdx.x;
    if (e >= N_EDGES) return;
    int s, d;
    if (g_is64) {
        s = (int)w[2 * (size_t)e];
        d = (int)w[2 * ((size_t)N_EDGES + e)];
    } else {
        s = (int)w[e];
        d = (int)w[(size_t)N_EDGES + e];
    }
    // defensive clamp: never let a bad index crash the container
    s = min(max(s, 0), N_NODES - 1);
    d = min(max(d, 0), N_NODES - 1);
    g_src[e] = s;
    g_dst[e] = d;
}

// ---------------- degree / normalization ----------------
__global__ void k_deg_init() {
    int i = blockIdx.x * blockDim.x + threadIdx.x;
    if (i < N_NODES) g_deg[i] = 1;           // self-loop
}

__global__ void k_deg_count() {
    int e = blockIdx.x * blockDim.x + threadIdx.x;
    if (e < N_EDGES) atomicAdd(&g_deg[g_dst[e]], 1);
}

__global__ void k_dinv() {
    int i = blockIdx.x * blockDim.x + threadIdx.x;
    if (i < N_NODES) g_dinv[i] = rsqrtf((float)g_deg[i]);
}

// ---------------- GEMM1: H1 = X @ W1 ; AGG1 = H1 * dinv^2 (self-loop seed) ----------------
// M=50000, K=500, N=128.  128x128 block tile, BK=8, 256 threads, 8x8 micro-tile.
__global__ void __launch_bounds__(256) k_gemm1(const float* __restrict__ X,
                                               const float* __restrict__ W1) {
    __shared__ float As[8][128];   // [k][m]
    __shared__ float Bs[8][128];   // [k][n]

    const int block_row = blockIdx.x * 128;
    const int tid = threadIdx.x;
    const int tr = tid >> 4;          // 0..15
    const int tc = tid & 15;          // 0..15

    const int a_row = tid >> 1;       // 0..127
    const int a_col = (tid & 1) * 4;  // 0 or 4
    const int b_row = tid >> 5;       // 0..7
    const int b_col = (tid & 31) * 4; // 0..124

    float acc[8][8];
#pragma unroll
    for (int i = 0; i < 8; i++)
#pragma unroll
        for (int j = 0; j < 8; j++) acc[i][j] = 0.f;

    for (int k0 = 0; k0 < F_IN; k0 += 8) {
        // load A tile (transposed into [k][m])
        float4 av = make_float4(0.f, 0.f, 0.f, 0.f);
        int gr = block_row + a_row;
        int gk = k0 + a_col;
        if (gr < N_NODES && gk < F_IN)
            av = *reinterpret_cast<const float4*>(X + (size_t)gr * F_IN + gk);
        As[a_col + 0][a_row] = av.x;
        As[a_col + 1][a_row] = av.y;
        As[a_col + 2][a_row] = av.z;
        As[a_col + 3][a_row] = av.w;

        // load B tile
        float4 bv = make_float4(0.f, 0.f, 0.f, 0.f);
        int bk = k0 + b_row;
        if (bk < F_IN)
            bv = *reinterpret_cast<const float4*>(W1 + bk * F_HID + b_col);
        *reinterpret_cast<float4*>(&Bs[b_row][b_col]) = bv;

        __syncthreads();

#pragma unroll
        for (int kk = 0; kk < 8; kk++) {
            float a[8], b[8];
            *reinterpret_cast<float4*>(&a[0]) = *reinterpret_cast<const float4*>(&As[kk][tr * 8]);
            *reinterpret_cast<float4*>(&a[4]) = *reinterpret_cast<const float4*>(&As[kk][tr * 8 + 4]);
            *reinterpret_cast<float4*>(&b[0]) = *reinterpret_cast<const float4*>(&Bs[kk][tc * 8]);
            *reinterpret_cast<float4*>(&b[4]) = *reinterpret_cast<const float4*>(&Bs[kk][tc * 8 + 4]);
#pragma unroll
            for (int i = 0; i < 8; i++)
#pragma unroll
                for (int j = 0; j < 8; j++)
                    acc[i][j] = fmaf(a[i], b[j], acc[i][j]);
        }
        __syncthreads();
    }

    // epilogue
#pragma unroll
    for (int i = 0; i < 8; i++) {
        int r = block_row + tr * 8 + i;
        if (r < N_NODES) {
            float s = g_dinv[r];
            s = s * s;
            int off = r * F_HID + tc * 8;
            float4 v0 = make_float4(acc[i][0], acc[i][1], acc[i][2], acc[i][3]);
            float4 v1 = make_float4(acc[i][4], acc[i][5], acc[i][6], acc[i][7]);
            *reinterpret_cast<float4*>(&g_H1[off])     = v0;
            *reinterpret_cast<float4*>(&g_H1[off + 4]) = v1;
            float4 w0 = make_float4(v0.x * s, v0.y * s, v0.z * s, v0.w * s);
            float4 w1 = make_float4(v1.x * s, v1.y * s, v1.z * s, v1.w * s);
            *reinterpret_cast<float4*>(&g_AGG1[off])     = w0;
            *reinterpret_cast<float4*>(&g_AGG1[off + 4]) = w1;
        }
    }
}

// ---------------- edge scatter layer1: AGG1[dst] += H1[src]*norm ----------------
// one warp per edge, each lane handles 4 contiguous features
__global__ void __launch_bounds__(256) k_scatter128() {
    int e = blockIdx.x * 8 + (threadIdx.x >> 5);
    if (e >= N_EDGES) return;
    int lane = threadIdx.x & 31;
    int s = g_src[e];
    int d = g_dst[e];
    float nrm = g_dinv[s] * g_dinv[d];
    const float4 v = *reinterpret_cast<const float4*>(g_H1 + (size_t)s * F_HID + lane * 4);
    float* dst = g_AGG1 + (size_t)d * F_HID + lane * 4;
    atomicAdd(dst + 0, v.x * nrm);
    atomicAdd(dst + 1, v.y * nrm);
    atomicAdd(dst + 2, v.z * nrm);
    atomicAdd(dst + 3, v.w * nrm);
}

// ---------------- GEMM2: H2 = relu(AGG1 + b1) @ W2 ; AGG2 = H2 * dinv^2 ----------------
// 128 rows per block, K=128 tiled by 32, N=48 (col 47 zero-padded)
__global__ void __launch_bounds__(256) k_gemm2(const float* __restrict__ b1v,
                                               const float* __restrict__ W2) {
    __shared__ float sIn[32][132];   // [k][r] padded
    __shared__ float sW[128][F_PAD]; // full W2, zero-padded col

    const int block_row = blockIdx.x * 128;
    const int tid = threadIdx.x;
    const int tr = tid >> 4;       // 0..15
    const int tc = tid & 15;       // 0..15
    const int r0 = tr * 8;
    const int c0 = tc * 3;         // 0..45 -> covers 48 cols

    // load W2 (padded)
    for (int i = tid; i < 128 * F_PAD; i += 256) {
        int k = i / F_PAD, c = i % F_PAD;
        sW[k][c] = (c < F_OUT) ? W2[k * F_OUT + c] : 0.f;
    }

    float acc[8][3];
#pragma unroll
    for (int i = 0; i < 8; i++)
#pragma unroll
        for (int j = 0; j < 3; j++) acc[i][j] = 0.f;

    for (int k0 = 0; k0 < F_HID; k0 += 32) {
        __syncthreads();
        // load 128 rows x 32 k of relu(AGG1 + b1), transposed into sIn[k][r]
#pragma unroll
        for (int t = 0; t < 4; t++) {
            int idx = tid + 256 * t;           // 0..1023
            int r = idx >> 3;                  // 0..127
            int kk4 = (idx & 7) * 4;           // 0..28
            int row = block_row + r;
            float4 v = make_float4(0.f, 0.f, 0.f, 0.f);
            if (row < N_NODES) {
                v = *reinterpret_cast<const float4*>(&g_AGG1[row * F_HID + k0 + kk4]);
                float4 bb = *reinterpret_cast<const float4*>(&b1v[k0 + kk4]);
                v.x = fmaxf(v.x + bb.x, 0.f);
                v.y = fmaxf(v.y + bb.y, 0.f);
                v.z = fmaxf(v.z + bb.z, 0.f);
                v.w = fmaxf(v.w + bb.w, 0.f);
            }
            sIn[kk4 + 0][r] = v.x;
            sIn[kk4 + 1][r] = v.y;
            sIn[kk4 + 2][r] = v.z;
            sIn[kk4 + 3][r] = v.w;
        }
        __syncthreads();

#pragma unroll
        for (int kk = 0; kk < 32; kk++) {
            float a[8], b[3];
            *reinterpret_cast<float4*>(&a[0]) = *reinterpret_cast<const float4*>(&sIn[kk][r0]);
            *reinterpret_cast<float4*>(&a[4]) = *reinterpret_cast<const float4*>(&sIn[kk][r0 + 4]);
            b[0] = sW[k0 + kk][c0 + 0];
            b[1] = sW[k0 + kk][c0 + 1];
            b[2] = sW[k0 + kk][c0 + 2];
#pragma unroll
            for (int i = 0; i < 8; i++)
#pragma unroll
                for (int j = 0; j < 3; j++)
                    acc[i][j] = fmaf(a[i], b[j], acc[i][j]);
        }
    }

#pragma unroll
    for (int i = 0; i < 8; i++) {
        int r = block_row + r0 + i;
        if (r < N_NODES) {
            float s = g_dinv[r];
            s = s * s;
#pragma unroll
            for (int j = 0; j < 3; j++) {
                int c = c0 + j;
                g_H2[r * F_PAD + c]   = acc[i][j];
                g_AGG2[r * F_PAD + c] = acc[i][j] * s;
            }
        }
    }
}

// ---------------- edge scatter layer2: AGG2[dst] += H2[src]*norm ----------------
__global__ void __launch_bounds__(256) k_scatter48() {
    int e = blockIdx.x * 8 + (threadIdx.x >> 5);
    if (e >= N_EDGES) return;
    int lane = threadIdx.x & 31;
    int s = g_src[e];
    int d = g_dst[e];
    float nrm = g_dinv[s] * g_dinv[d];
    const float* src = g_H2 + (size_t)s * F_PAD;
    float* dst = g_AGG2 + (size_t)d * F_PAD;
    atomicAdd(dst + lane, src[lane] * nrm);
    int c2 = lane + 32;
    if (c2 < F_OUT) atomicAdd(dst + c2, src[c2] * nrm);
}

// ---------------- bias2 + log_softmax ----------------
__global__ void __launch_bounds__(256) k_out(const float* __restrict__ b2,
                                             float* __restrict__ out) {
    int r = blockIdx.x * 8 + (threadIdx.x >> 5);
    if (r >= N_NODES) return;
    int lane = threadIdx.x & 31;

    float z1 = g_AGG2[r * F_PAD + lane] + b2[lane];      // lane < 32 < 47 always valid
    int c2 = lane + 32;
    float z2 = (c2 < F_OUT) ? (g_AGG2[r * F_PAD + c2] + b2[c2]) : -3.0e38f;

    float m = fmaxf(z1, z2);
#pragma unroll
    for (int o = 16; o; o >>= 1) m = fmaxf(m, __shfl_xor_sync(0xffffffffu, m, o));

    float esum = expf(z1 - m) + ((c2 < F_OUT) ? expf(z2 - m) : 0.f);
#pragma unroll
    for (int o = 16; o; o >>= 1) esum += __shfl_xor_sync(0xffffffffu, esum, o);

    float lse = m + logf(esum);
    out[r * F_OUT + lane] = z1 - lse;
    if (c2 < F_OUT) out[r * F_OUT + c2] = z2 - lse;
}

// ---------------- launch ----------------
extern "C" void kernel_launch(void* const* d_in, const int* in_sizes, int n_in,
                              void* d_out, int out_size) {
    // map inputs by element count (robust to ordering)
    const float* x = 0; const float* W1 = 0; const float* b1 = 0;
    const float* W2 = 0; const float* b2 = 0; const void* ei = 0;
    for (int i = 0; i < n_in; i++) {
        switch (in_sizes[i]) {
            case 25000000: x  = (const float*)d_in[i]; break;
            case 64000:    W1 = (const float*)d_in[i]; break;
            case 128:      b1 = (const float*)d_in[i]; break;
            case 6016:     W2 = (const float*)d_in[i]; break;
            case 47:       b2 = (const float*)d_in[i]; break;
            case 1600000:  ei = d_in[i]; break;
            default: break;
        }
    }
    float* out = (float*)d_out;

    k_detect   <<<1, 128>>>((const unsigned int*)ei);
    k_convert  <<<(N_EDGES + 255) / 256, 256>>>((const unsigned int*)ei);

    k_deg_init <<<(N_NODES + 255) / 256, 256>>>();
    k_deg_count<<<(N_EDGES + 255) / 256, 256>>>();
    k_dinv     <<<(N_NODES + 255) / 256, 256>>>();

    k_gemm1    <<<(N_NODES + 127) / 128, 256>>>(x, W1);
    k_scatter128<<<(N_EDGES + 7) / 8, 256>>>();

    k_gemm2    <<<(N_NODES + 127) / 128, 256>>>(b1, W2);
    k_scatter48<<<(N_EDGES + 7) / 8, 256>>>();

    k_out      <<<(N_NODES + 7) / 8, 256>>>(b2, out);
}

// round 3
// speedup vs baseline: 1.3921x; 1.3921x over previous
#include <cuda_runtime.h>
#include <math.h>

#define N_NODES 50000
#define N_EDGES 800000
#define F_IN    500
#define F_HID   128
#define F_OUT   47
#define F_PAD   48

// ---------------- scratch (static device arrays only) ----------------
__device__ float g_H1  [(size_t)N_NODES * F_HID];   // X@W1
__device__ float g_AGG1[(size_t)N_NODES * F_HID];   // relu(agg1 + b1)
__device__ float g_H2  [(size_t)N_NODES * F_PAD];   // AGG1@W2 (padded, col47=0)
__device__ int   g_deg [N_NODES];                   // real in-degree (no self loop)
__device__ float g_dinv[N_NODES];                   // rsqrt(deg+1)
__device__ int   g_off [N_NODES + 1];               // CSR offsets (by dst)
__device__ int   g_cur [N_NODES];                   // bucket cursors
__device__ int   g_bsrc[N_EDGES];                   // bucketed src
__device__ float g_bnrm[N_EDGES];                   // bucketed edge norm
__device__ int   g_is64;

// ---------------- 0: zero degrees + detect edge dtype ----------------
// int64 indices < 50000 => every odd 32-bit word is 0; int32 => essentially never.
__global__ void k_detect_init(const unsigned int* __restrict__ w) {
    int i = blockIdx.x * blockDim.x + threadIdx.x;
    if (i < N_NODES) g_deg[i] = 0;
    if (blockIdx.x == 0) {
        __shared__ int nz;
        if (threadIdx.x == 0) nz = 0;
        __syncthreads();
        if (threadIdx.x < 128 && w[2 * threadIdx.x + 1] != 0u) atomicAdd(&nz, 1);
        __syncthreads();
        if (threadIdx.x == 0) g_is64 = (nz == 0) ? 1 : 0;
    }
}

// ---------------- 1: count in-degrees ----------------
__global__ void k_count(const unsigned int* __restrict__ w) {
    int e = blockIdx.x * blockDim.x + threadIdx.x;
    if (e >= N_EDGES) return;
    int d = g_is64 ? (int)w[2 * ((size_t)N_EDGES + e)] : (int)w[(size_t)N_EDGES + e];
    d = min(max(d, 0), N_NODES - 1);
    atomicAdd(&g_deg[d], 1);
}

// ---------------- 2: prefix scan -> offsets, cursors, dinv ----------------
__global__ void __launch_bounds__(1024) k_scan() {
    __shared__ int sums[1024];
    const int t = threadIdx.x;
    const int CH = (N_NODES + 1023) / 1024;     // 49
    int lo = t * CH, hi = min(lo + CH, N_NODES);
    int s = 0;
    for (int i = lo; i < hi; i++) s += g_deg[i];
    sums[t] = s;
    __syncthreads();
    for (int ofs = 1; ofs < 1024; ofs <<= 1) {
        int v = (t >= ofs) ? sums[t - ofs] : 0;
        __syncthreads();
        sums[t] += v;
        __syncthreads();
    }
    int run = (t == 0) ? 0 : sums[t - 1];
    for (int i = lo; i < hi; i++) {
        int d = g_deg[i];
        g_off[i] = run;
        g_cur[i] = run;
        g_dinv[i] = rsqrtf((float)(d + 1));
        run += d;
    }
    if (t == 1023) g_off[N_NODES] = run;
}

// ---------------- 3: GEMM1  H1 = X @ W1  (double-buffered SIMT) ----------------
__global__ void __launch_bounds__(256) k_gemm1(const float* __restrict__ X,
                                               const float* __restrict__ W1) {
    __shared__ float As[2][8][128];   // [buf][k][m]
    __shared__ float Bs[2][8][128];   // [buf][k][n]

    const int block_row = blockIdx.x * 128;
    const int tid = threadIdx.x;
    const int tr = tid >> 4, tc = tid & 15;
    const int a_row = tid >> 1, a_col = (tid & 1) * 4;
    const int b_row = tid >> 5, b_col = (tid & 31) * 4;

    float acc[8][8];
#pragma unroll
    for (int i = 0; i < 8; i++)
#pragma unroll
        for (int j = 0; j < 8; j++) acc[i][j] = 0.f;

    float4 av, bv;

#define G1_LOAD(K0)                                                            \
    {                                                                          \
        av = make_float4(0.f, 0.f, 0.f, 0.f);                                  \
        bv = make_float4(0.f, 0.f, 0.f, 0.f);                                  \
        int gr = block_row + a_row, gk = (K0) + a_col;                         \
        if (gr < N_NODES && gk < F_IN)                                         \
            av = *reinterpret_cast<const float4*>(X + (size_t)gr * F_IN + gk); \
        int bk = (K0) + b_row;                                                 \
        if (bk < F_IN)                                                         \
            bv = *reinterpret_cast<const float4*>(W1 + bk * F_HID + b_col);    \
    }

#define G1_STORE(BUF)                                                          \
    {                                                                          \
        As[BUF][a_col + 0][a_row] = av.x;                                      \
        As[BUF][a_col + 1][a_row] = av.y;                                      \
        As[BUF][a_col + 2][a_row] = av.z;                                      \
        As[BUF][a_col + 3][a_row] = av.w;                                      \
        *reinterpret_cast<float4*>(&Bs[BUF][b_row][b_col]) = bv;               \
    }

#define G1_COMPUTE(BUF)                                                        \
    {                                                                          \
        _Pragma("unroll") for (int kk = 0; kk < 8; kk++) {                     \
            float a[8], b[8];                                                  \
            *reinterpret_cast<float4*>(&a[0]) =                                \
                *reinterpret_cast<const float4*>(&As[BUF][kk][tr * 8]);        \
            *reinterpret_cast<float4*>(&a[4]) =                                \
                *reinterpret_cast<const float4*>(&As[BUF][kk][tr * 8 + 4]);    \
            *reinterpret_cast<float4*>(&b[0]) =                                \
                *reinterpret_cast<const float4*>(&Bs[BUF][kk][tc * 8]);        \
            *reinterpret_cast<float4*>(&b[4]) =                                \
                *reinterpret_cast<const float4*>(&Bs[BUF][kk][tc * 8 + 4]);    \
            _Pragma("unroll") for (int i = 0; i < 8; i++)                      \
                _Pragma("unroll") for (int j = 0; j < 8; j++)                  \
                    acc[i][j] = fmaf(a[i], b[j], acc[i][j]);                   \
        }                                                                      \
    }

    G1_LOAD(0);
    G1_STORE(0);
    __syncthreads();

    int cur = 0;
    for (int k0 = 8; k0 < F_IN; k0 += 8) {
        G1_LOAD(k0);
        G1_COMPUTE(cur);
        G1_STORE(1 - cur);
        __syncthreads();
        cur ^= 1;
    }
    G1_COMPUTE(cur);

#pragma unroll
    for (int i = 0; i < 8; i++) {
        int r = block_row + tr * 8 + i;
        if (r < N_NODES) {
            int off = r * F_HID + tc * 8;
            *reinterpret_cast<float4*>(&g_H1[off]) =
                make_float4(acc[i][0], acc[i][1], acc[i][2], acc[i][3]);
            *reinterpret_cast<float4*>(&g_H1[off + 4]) =
                make_float4(acc[i][4], acc[i][5], acc[i][6], acc[i][7]);
        }
    }
}

// ---------------- 4: bucket edges by dst ----------------
__global__ void k_bucket(const unsigned int* __restrict__ w) {
    int e = blockIdx.x * blockDim.x + threadIdx.x;
    if (e >= N_EDGES) return;
    int s, d;
    if (g_is64) {
        s = (int)w[2 * (size_t)e];
        d = (int)w[2 * ((size_t)N_EDGES + e)];
    } else {
        s = (int)w[e];
        d = (int)w[(size_t)N_EDGES + e];
    }
    s = min(max(s, 0), N_NODES - 1);
    d = min(max(d, 0), N_NODES - 1);
    float nrm = g_dinv[s] * g_dinv[d];
    int pos = atomicAdd(&g_cur[d], 1);
    g_bsrc[pos] = s;
    g_bnrm[pos] = nrm;
}

// ---------------- 5: gather layer1 + bias + relu  (warp per node) ----------------
__global__ void __launch_bounds__(256) k_gather1(const float* __restrict__ b1) {
    int d = blockIdx.x * 8 + (threadIdx.x >> 5);
    if (d >= N_NODES) return;
    int lane = threadIdx.x & 31;
    float di = g_dinv[d];
    float self = di * di;
    const float4 h = *reinterpret_cast<const float4*>(g_H1 + (size_t)d * F_HID + lane * 4);
    float4 acc = make_float4(h.x * self, h.y * self, h.z * self, h.w * self);

    int j = g_off[d], jend = g_off[d + 1];
    for (; j + 1 < jend; j += 2) {
        int s0 = g_bsrc[j], s1 = g_bsrc[j + 1];
        float w0 = g_bnrm[j], w1 = g_bnrm[j + 1];
        float4 v0 = *reinterpret_cast<const float4*>(g_H1 + (size_t)s0 * F_HID + lane * 4);
        float4 v1 = *reinterpret_cast<const float4*>(g_H1 + (size_t)s1 * F_HID + lane * 4);
        acc.x += v0.x * w0 + v1.x * w1;
        acc.y += v0.y * w0 + v1.y * w1;
        acc.z += v0.z * w0 + v1.z * w1;
        acc.w += v0.w * w0 + v1.w * w1;
    }
    if (j < jend) {
        int s0 = g_bsrc[j];
        float w0 = g_bnrm[j];
        float4 v0 = *reinterpret_cast<const float4*>(g_H1 + (size_t)s0 * F_HID + lane * 4);
        acc.x += v0.x * w0; acc.y += v0.y * w0; acc.z += v0.z * w0; acc.w += v0.w * w0;
    }
    float4 bb = *reinterpret_cast<const float4*>(b1 + lane * 4);
    acc.x = fmaxf(acc.x + bb.x, 0.f);
    acc.y = fmaxf(acc.y + bb.y, 0.f);
    acc.z = fmaxf(acc.z + bb.z, 0.f);
    acc.w = fmaxf(acc.w + bb.w, 0.f);
    *reinterpret_cast<float4*>(g_AGG1 + (size_t)d * F_HID + lane * 4) = acc;
}

// ---------------- 6: GEMM2  H2 = AGG1 @ W2  (N=48 padded) ----------------
__global__ void __launch_bounds__(256) k_gemm2(const float* __restrict__ W2) {
    __shared__ float sIn[32][132];
    __shared__ float sW[128][F_PAD];

    const int block_row = blockIdx.x * 128;
    const int tid = threadIdx.x;
    const int tr = tid >> 4, tc = tid & 15;
    const int r0 = tr * 8, c0 = tc * 3;

    for (int i = tid; i < 128 * F_PAD; i += 256) {
        int k = i / F_PAD, c = i % F_PAD;
        sW[k][c] = (c < F_OUT) ? W2[k * F_OUT + c] : 0.f;
    }

    float acc[8][3];
#pragma unroll
    for (int i = 0; i < 8; i++)
#pragma unroll
        for (int j = 0; j < 3; j++) acc[i][j] = 0.f;

    for (int k0 = 0; k0 < F_HID; k0 += 32) {
        __syncthreads();
#pragma unroll
        for (int t = 0; t < 4; t++) {
            int idx = tid + 256 * t;
            int r = idx >> 3;
            int kk4 = (idx & 7) * 4;
            int row = block_row + r;
            float4 v = make_float4(0.f, 0.f, 0.f, 0.f);
            if (row < N_NODES)
                v = *reinterpret_cast<const float4*>(&g_AGG1[row * F_HID + k0 + kk4]);
            sIn[kk4 + 0][r] = v.x;
            sIn[kk4 + 1][r] = v.y;
            sIn[kk4 + 2][r] = v.z;
            sIn[kk4 + 3][r] = v.w;
        }
        __syncthreads();

#pragma unroll
        for (int kk = 0; kk < 32; kk++) {
            float a[8], b[3];
            *reinterpret_cast<float4*>(&a[0]) = *reinterpret_cast<const float4*>(&sIn[kk][r0]);
            *reinterpret_cast<float4*>(&a[4]) = *reinterpret_cast<const float4*>(&sIn[kk][r0 + 4]);
            b[0] = sW[k0 + kk][c0 + 0];
            b[1] = sW[k0 + kk][c0 + 1];
            b[2] = sW[k0 + kk][c0 + 2];
#pragma unroll
            for (int i = 0; i < 8; i++)
#pragma unroll
                for (int j = 0; j < 3; j++)
                    acc[i][j] = fmaf(a[i], b[j], acc[i][j]);
        }
    }

#pragma unroll
    for (int i = 0; i < 8; i++) {
        int r = block_row + r0 + i;
        if (r < N_NODES)
#pragma unroll
            for (int j = 0; j < 3; j++)
                g_H2[r * F_PAD + c0 + j] = acc[i][j];
    }
}

// ---------------- 7: gather layer2 + bias + log_softmax -> out ----------------
__global__ void __launch_bounds__(256) k_gather2_out(const float* __restrict__ b2,
                                                     float* __restrict__ out) {
    int d = blockIdx.x * 8 + (threadIdx.x >> 5);
    if (d >= N_NODES) return;
    int lane = threadIdx.x & 31;
    int c1 = lane + 32;
    bool has2 = (c1 < F_OUT);

    float di = g_dinv[d];
    float self = di * di;
    const float* hr = g_H2 + (size_t)d * F_PAD;
    float a0 = hr[lane] * self;
    float a1 = has2 ? hr[c1] * self : 0.f;

    int j = g_off[d], jend = g_off[d + 1];
    for (; j < jend; j++) {
        int s = g_bsrc[j];
        float w = g_bnrm[j];
        const float* sr = g_H2 + (size_t)s * F_PAD;
        a0 += sr[lane] * w;
        if (has2) a1 += sr[c1] * w;
    }

    float z0 = a0 + b2[lane];
    float z1 = has2 ? (a1 + b2[c1]) : -3.0e38f;

    float m = fmaxf(z0, z1);
#pragma unroll
    for (int o = 16; o; o >>= 1) m = fmaxf(m, __shfl_xor_sync(0xffffffffu, m, o));
    float esum = expf(z0 - m) + (has2 ? expf(z1 - m) : 0.f);
#pragma unroll
    for (int o = 16; o; o >>= 1) esum += __shfl_xor_sync(0xffffffffu, esum, o);
    float lse = m + logf(esum);

    out[(size_t)d * F_OUT + lane] = z0 - lse;
    if (has2) out[(size_t)d * F_OUT + c1] = z1 - lse;
}

// ---------------- launch ----------------
extern "C" void kernel_launch(void* const* d_in, const int* in_sizes, int n_in,
                              void* d_out, int out_size) {
    const float* x = 0; const float* W1 = 0; const float* b1 = 0;
    const float* W2 = 0; const float* b2 = 0; const void* ei = 0;
    for (int i = 0; i < n_in; i++) {
        switch (in_sizes[i]) {
            case 25000000: x  = (const float*)d_in[i]; break;
            case 64000:    W1 = (const float*)d_in[i]; break;
            case 128:      b1 = (const float*)d_in[i]; break;
            case 6016:     W2 = (const float*)d_in[i]; break;
            case 47:       b2 = (const float*)d_in[i]; break;
            case 1600000:  ei = d_in[i]; break;
            default: break;
        }
    }
    float* out = (float*)d_out;
    const unsigned int* w = (const unsigned int*)ei;

    k_detect_init<<<(N_NODES + 255) / 256, 256>>>(w);
    k_count      <<<(N_EDGES + 255) / 256, 256>>>(w);
    k_scan       <<<1, 1024>>>();
    k_gemm1      <<<(N_NODES + 127) / 128, 256>>>(x, W1);
    k_bucket     <<<(N_EDGES + 255) / 256, 256>>>(w);
    k_gather1    <<<(N_NODES + 7) / 8, 256>>>(b1);
    k_gemm2      <<<(N_NODES + 127) / 128, 256>>>(W2);
    k_gather2_out<<<(N_NODES + 7) / 8, 256>>>(b2, out);
}

// round 4
// speedup vs baseline: 1.6590x; 1.1917x over previous
#include <cuda_runtime.h>
#include <math.h>

#define N_NODES 50000
#define N_EDGES 800000
#define F_IN    500
#define F_HID   128
#define F_OUT   47
#define F_PAD   48

typedef unsigned long long u64;

// ---------------- packed f32x2 helpers (Blackwell FFMA2, PTX-only) ----------------
__device__ __forceinline__ u64 dup_f32(float v) {
    u64 r;
    asm("mov.b64 %0, {%1, %1};" : "=l"(r) : "f"(v));
    return r;
}
__device__ __forceinline__ void fma2(u64& d, u64 a, u64 b) {
    asm("fma.rn.f32x2 %0, %1, %2, %0;" : "+l"(d) : "l"(a), "l"(b));
}
__device__ __forceinline__ float f32x2_lo(u64 v) {
    float lo;
    asm("{ .reg .f32 hi; mov.b64 {%0, hi}, %1; }" : "=f"(lo) : "l"(v));
    return lo;
}
__device__ __forceinline__ float f32x2_hi(u64 v) {
    float hi;
    asm("{ .reg .f32 lo; mov.b64 {lo, %0}, %1; }" : "=f"(hi) : "l"(v));
    return hi;
}

// ---------------- scratch (static device arrays only) ----------------
__device__ float g_H1  [(size_t)N_NODES * F_HID];   // X@W1
__device__ float g_AGG1[(size_t)N_NODES * F_HID];   // relu(agg1 + b1)
__device__ float g_H2  [(size_t)N_NODES * F_PAD];   // AGG1@W2 (padded, col47=0)
__device__ int   g_deg [N_NODES];
__device__ float g_dinv[N_NODES];
__device__ int   g_off [N_NODES + 1];
__device__ int   g_cur [N_NODES];
__device__ int   g_bsrc[N_EDGES];
__device__ float g_bnrm[N_EDGES];
__device__ int   g_is64;

// ---------------- 0: zero degrees + detect edge dtype ----------------
__global__ void k_detect_init(const unsigned int* __restrict__ w) {
    int i = blockIdx.x * blockDim.x + threadIdx.x;
    if (i < N_NODES) g_deg[i] = 0;
    if (blockIdx.x == 0) {
        __shared__ int nz;
        if (threadIdx.x == 0) nz = 0;
        __syncthreads();
        if (threadIdx.x < 128 && w[2 * threadIdx.x + 1] != 0u) atomicAdd(&nz, 1);
        __syncthreads();
        if (threadIdx.x == 0) g_is64 = (nz == 0) ? 1 : 0;
    }
}

// ---------------- 1: count in-degrees ----------------
__global__ void k_count(const unsigned int* __restrict__ w) {
    int e = blockIdx.x * blockDim.x + threadIdx.x;
    if (e >= N_EDGES) return;
    int d = g_is64 ? (int)w[2 * ((size_t)N_EDGES + e)] : (int)w[(size_t)N_EDGES + e];
    d = min(max(d, 0), N_NODES - 1);
    atomicAdd(&g_deg[d], 1);
}

// ---------------- 2: prefix scan -> offsets, cursors, dinv ----------------
__global__ void __launch_bounds__(1024) k_scan() {
    __shared__ int sums[1024];
    const int t = threadIdx.x;
    const int CH = (N_NODES + 1023) / 1024;
    int lo = t * CH, hi = min(lo + CH, N_NODES);
    int s = 0;
    for (int i = lo; i < hi; i++) s += g_deg[i];
    sums[t] = s;
    __syncthreads();
    for (int ofs = 1; ofs < 1024; ofs <<= 1) {
        int v = (t >= ofs) ? sums[t - ofs] : 0;
        __syncthreads();
        sums[t] += v;
        __syncthreads();
    }
    int run = (t == 0) ? 0 : sums[t - 1];
    for (int i = lo; i < hi; i++) {
        int d = g_deg[i];
        g_off[i] = run;
        g_cur[i] = run;
        g_dinv[i] = rsqrtf((float)(d + 1));
        run += d;
    }
    if (t == 1023) g_off[N_NODES] = run;
}

// ---------------- 3: GEMM1  H1 = X @ W1  (double-buffered, packed f32x2) ----------------
__global__ void __launch_bounds__(256) k_gemm1(const float* __restrict__ X,
                                               const float* __restrict__ W1) {
    __shared__ float As[2][8][128];   // [buf][k][m]
    __shared__ float Bs[2][8][128];   // [buf][k][n]

    const int block_row = blockIdx.x * 128;
    const int tid = threadIdx.x;
    const int tr = tid >> 4, tc = tid & 15;
    const int a_row = tid >> 1, a_col = (tid & 1) * 4;
    const int b_row = tid >> 5, b_col = (tid & 31) * 4;

    // acc2[ip][j] packs output rows (tr*8+2ip, tr*8+2ip+1) for column tc*8+j
    u64 acc2[4][8];
#pragma unroll
    for (int i = 0; i < 4; i++)
#pragma unroll
        for (int j = 0; j < 8; j++) acc2[i][j] = 0ull;

    float4 av, bv;

#define G1_LOAD(K0)                                                            \
    {                                                                          \
        av = make_float4(0.f, 0.f, 0.f, 0.f);                                  \
        bv = make_float4(0.f, 0.f, 0.f, 0.f);                                  \
        int gr = block_row + a_row, gk = (K0) + a_col;                         \
        if (gr < N_NODES && gk < F_IN)                                         \
            av = *reinterpret_cast<const float4*>(X + (size_t)gr * F_IN + gk); \
        int bk = (K0) + b_row;                                                 \
        if (bk < F_IN)                                                         \
            bv = *reinterpret_cast<const float4*>(W1 + bk * F_HID + b_col);    \
    }

#define G1_STORE(BUF)                                                          \
    {                                                                          \
        As[BUF][a_col + 0][a_row] = av.x;                                      \
        As[BUF][a_col + 1][a_row] = av.y;                                      \
        As[BUF][a_col + 2][a_row] = av.z;                                      \
        As[BUF][a_col + 3][a_row] = av.w;                                      \
        *reinterpret_cast<float4*>(&Bs[BUF][b_row][b_col]) = bv;               \
    }

#define G1_COMPUTE(BUF)                                                        \
    {                                                                          \
        _Pragma("unroll") for (int kk = 0; kk < 8; kk++) {                     \
            ulonglong2 ap01 =                                                  \
                *reinterpret_cast<const ulonglong2*>(&As[BUF][kk][tr * 8]);    \
            ulonglong2 ap23 =                                                  \
                *reinterpret_cast<const ulonglong2*>(&As[BUF][kk][tr * 8 + 4]);\
            float bl[8];                                                       \
            *reinterpret_cast<float4*>(&bl[0]) =                               \
                *reinterpret_cast<const float4*>(&Bs[BUF][kk][tc * 8]);        \
            *reinterpret_cast<float4*>(&bl[4]) =                               \
                *reinterpret_cast<const float4*>(&Bs[BUF][kk][tc * 8 + 4]);    \
            _Pragma("unroll") for (int j = 0; j < 8; j++) {                    \
                u64 bd = dup_f32(bl[j]);                                       \
                fma2(acc2[0][j], ap01.x, bd);                                  \
                fma2(acc2[1][j], ap01.y, bd);                                  \
                fma2(acc2[2][j], ap23.x, bd);                                  \
                fma2(acc2[3][j], ap23.y, bd);                                  \
            }                                                                  \
        }                                                                      \
    }

    G1_LOAD(0);
    G1_STORE(0);
    __syncthreads();

    int cur = 0;
    for (int k0 = 8; k0 < F_IN; k0 += 8) {
        G1_LOAD(k0);
        G1_COMPUTE(cur);
        G1_STORE(1 - cur);
        __syncthreads();
        cur ^= 1;
    }
    G1_COMPUTE(cur);

#pragma unroll
    for (int i = 0; i < 8; i++) {
        int r = block_row + tr * 8 + i;
        if (r < N_NODES) {
            int ip = i >> 1;
            float v[8];
#pragma unroll
            for (int j = 0; j < 8; j++)
                v[j] = (i & 1) ? f32x2_hi(acc2[ip][j]) : f32x2_lo(acc2[ip][j]);
            int off = r * F_HID + tc * 8;
            *reinterpret_cast<float4*>(&g_H1[off])     = make_float4(v[0], v[1], v[2], v[3]);
            *reinterpret_cast<float4*>(&g_H1[off + 4]) = make_float4(v[4], v[5], v[6], v[7]);
        }
    }
}

// ---------------- 4: bucket edges by dst ----------------
__global__ void k_bucket(const unsigned int* __restrict__ w) {
    int e = blockIdx.x * blockDim.x + threadIdx.x;
    if (e >= N_EDGES) return;
    int s, d;
    if (g_is64) {
        s = (int)w[2 * (size_t)e];
        d = (int)w[2 * ((size_t)N_EDGES + e)];
    } else {
        s = (int)w[e];
        d = (int)w[(size_t)N_EDGES + e];
    }
    s = min(max(s, 0), N_NODES - 1);
    d = min(max(d, 0), N_NODES - 1);
    float nrm = g_dinv[s] * g_dinv[d];
    int pos = atomicAdd(&g_cur[d], 1);
    g_bsrc[pos] = s;
    g_bnrm[pos] = nrm;
}

// ---------------- 5: gather layer1 + bias + relu  (warp per node) ----------------
__global__ void __launch_bounds__(256) k_gather1(const float* __restrict__ b1) {
    int d = blockIdx.x * 8 + (threadIdx.x >> 5);
    if (d >= N_NODES) return;
    int lane = threadIdx.x & 31;
    float di = g_dinv[d];
    float self = di * di;
    const float4 h = *reinterpret_cast<const float4*>(g_H1 + (size_t)d * F_HID + lane * 4);
    float4 acc = make_float4(h.x * self, h.y * self, h.z * self, h.w * self);

    int j = g_off[d], jend = g_off[d + 1];
    for (; j + 1 < jend; j += 2) {
        int s0 = g_bsrc[j], s1 = g_bsrc[j + 1];
        float w0 = g_bnrm[j], w1 = g_bnrm[j + 1];
        float4 v0 = *reinterpret_cast<const float4*>(g_H1 + (size_t)s0 * F_HID + lane * 4);
        float4 v1 = *reinterpret_cast<const float4*>(g_H1 + (size_t)s1 * F_HID + lane * 4);
        acc.x += v0.x * w0 + v1.x * w1;
        acc.y += v0.y * w0 + v1.y * w1;
        acc.z += v0.z * w0 + v1.z * w1;
        acc.w += v0.w * w0 + v1.w * w1;
    }
    if (j < jend) {
        int s0 = g_bsrc[j];
        float w0 = g_bnrm[j];
        float4 v0 = *reinterpret_cast<const float4*>(g_H1 + (size_t)s0 * F_HID + lane * 4);
        acc.x += v0.x * w0; acc.y += v0.y * w0; acc.z += v0.z * w0; acc.w += v0.w * w0;
    }
    float4 bb = *reinterpret_cast<const float4*>(b1 + lane * 4);
    acc.x = fmaxf(acc.x + bb.x, 0.f);
    acc.y = fmaxf(acc.y + bb.y, 0.f);
    acc.z = fmaxf(acc.z + bb.z, 0.f);
    acc.w = fmaxf(acc.w + bb.w, 0.f);
    *reinterpret_cast<float4*>(g_AGG1 + (size_t)d * F_HID + lane * 4) = acc;
}

// ---------------- 6: GEMM2  H2 = AGG1 @ W2  (N=48 padded, packed f32x2) ----------------
__global__ void __launch_bounds__(256) k_gemm2(const float* __restrict__ W2) {
    __shared__ float sIn[32][132];
    __shared__ float sW[128][F_PAD];

    const int block_row = blockIdx.x * 128;
    const int tid = threadIdx.x;
    const int tr = tid >> 4, tc = tid & 15;
    const int r0 = tr * 8, c0 = tc * 3;

    for (int i = tid; i < 128 * F_PAD; i += 256) {
        int k = i / F_PAD, c = i % F_PAD;
        sW[k][c] = (c < F_OUT) ? W2[k * F_OUT + c] : 0.f;
    }

    // acc2[ip][j]: rows (r0+2ip, r0+2ip+1), col c0+j
    u64 acc2[4][3];
#pragma unroll
    for (int i = 0; i < 4; i++)
#pragma unroll
        for (int j = 0; j < 3; j++) acc2[i][j] = 0ull;

    for (int k0 = 0; k0 < F_HID; k0 += 32) {
        __syncthreads();
#pragma unroll
        for (int t = 0; t < 4; t++) {
            int idx = tid + 256 * t;
            int r = idx >> 3;
            int kk4 = (idx & 7) * 4;
            int row = block_row + r;
            float4 v = make_float4(0.f, 0.f, 0.f, 0.f);
            if (row < N_NODES)
                v = *reinterpret_cast<const float4*>(&g_AGG1[row * F_HID + k0 + kk4]);
            sIn[kk4 + 0][r] = v.x;
            sIn[kk4 + 1][r] = v.y;
            sIn[kk4 + 2][r] = v.z;
            sIn[kk4 + 3][r] = v.w;
        }
        __syncthreads();

#pragma unroll
        for (int kk = 0; kk < 32; kk++) {
            ulonglong2 ap01 = *reinterpret_cast<const ulonglong2*>(&sIn[kk][r0]);
            ulonglong2 ap23 = *reinterpret_cast<const ulonglong2*>(&sIn[kk][r0 + 4]);
#pragma unroll
            for (int j = 0; j < 3; j++) {
                u64 bd = dup_f32(sW[k0 + kk][c0 + j]);
                fma2(acc2[0][j], ap01.x, bd);
                fma2(acc2[1][j], ap01.y, bd);
                fma2(acc2[2][j], ap23.x, bd);
                fma2(acc2[3][j], ap23.y, bd);
            }
        }
    }

#pragma unroll
    for (int i = 0; i < 8; i++) {
        int r = block_row + r0 + i;
        if (r < N_NODES) {
            int ip = i >> 1;
#pragma unroll
            for (int j = 0; j < 3; j++) {
                float v = (i & 1) ? f32x2_hi(acc2[ip][j]) : f32x2_lo(acc2[ip][j]);
                g_H2[r * F_PAD + c0 + j] = v;
            }
        }
    }
}

// ---------------- 7: gather layer2 + bias + log_softmax -> out ----------------
__global__ void __launch_bounds__(256) k_gather2_out(const float* __restrict__ b2,
                                                     float* __restrict__ out) {
    int d = blockIdx.x * 8 + (threadIdx.x >> 5);
    if (d >= N_NODES) return;
    int lane = threadIdx.x & 31;
    int c1 = lane + 32;
    bool has2 = (c1 < F_OUT);

    float di = g_dinv[d];
    float self = di * di;
    const float* hr = g_H2 + (size_t)d * F_PAD;
    float a0 = hr[lane] * self;
    float a1 = has2 ? hr[c1] * self : 0.f;

    int j = g_off[d], jend = g_off[d + 1];
    for (; j < jend; j++) {
        int s = g_bsrc[j];
        float w = g_bnrm[j];
        const float* sr = g_H2 + (size_t)s * F_PAD;
        a0 += sr[lane] * w;
        if (has2) a1 += sr[c1] * w;
    }

    float z0 = a0 + b2[lane];
    float z1 = has2 ? (a1 + b2[c1]) : -3.0e38f;

    float m = fmaxf(z0, z1);
#pragma unroll
    for (int o = 16; o; o >>= 1) m = fmaxf(m, __shfl_xor_sync(0xffffffffu, m, o));
    float esum = expf(z0 - m) + (has2 ? expf(z1 - m) : 0.f);
#pragma unroll
    for (int o = 16; o; o >>= 1) esum += __shfl_xor_sync(0xffffffffu, esum, o);
    float lse = m + logf(esum);

    out[(size_t)d * F_OUT + lane] = z0 - lse;
    if (has2) out[(size_t)d * F_OUT + c1] = z1 - lse;
}

// ---------------- launch ----------------
extern "C" void kernel_launch(void* const* d_in, const int* in_sizes, int n_in,
                              void* d_out, int out_size) {
    const float* x = 0; const float* W1 = 0; const float* b1 = 0;
    const float* W2 = 0; const float* b2 = 0; const void* ei = 0;
    for (int i = 0; i < n_in; i++) {
        switch (in_sizes[i]) {
            case 25000000: x  = (const float*)d_in[i]; break;
            case 64000:    W1 = (const float*)d_in[i]; break;
            case 128:      b1 = (const float*)d_in[i]; break;
            case 6016:     W2 = (const float*)d_in[i]; break;
            case 47:       b2 = (const float*)d_in[i]; break;
            case 1600000:  ei = d_in[i]; break;
            default: break;
        }
    }
    float* out = (float*)d_out;
    const unsigned int* w = (const unsigned int*)ei;

    k_detect_init<<<(N_NODES + 255) / 256, 256>>>(w);
    k_count      <<<(N_EDGES + 255) / 256, 256>>>(w);
    k_scan       <<<1, 1024>>>();
    k_gemm1      <<<(N_NODES + 127) / 128, 256>>>(x, W1);
    k_bucket     <<<(N_EDGES + 255) / 256, 256>>>(w);
    k_gather1    <<<(N_NODES + 7) / 8, 256>>>(b1);
    k_gemm2      <<<(N_NODES + 127) / 128, 256>>>(W2);
    k_gather2_out<<<(N_NODES + 7) / 8, 256>>>(b2, out);
}

// round 7
// speedup vs baseline: 1.6851x; 1.0157x over previous
#include <cuda_runtime.h>
#include <math.h>
#include <stdint.h>

#define N_NODES 50000
#define N_EDGES 800000
#define F_IN    500
#define F_HID   128
#define F_OUT   47
#define F_PAD   48

typedef unsigned long long u64;

// ---------------- packed f32x2 helpers (Blackwell FFMA2, PTX-only) ----------------
__device__ __forceinline__ u64 dup_f32(float v) {
    u64 r;
    asm("mov.b64 %0, {%1, %1};" : "=l"(r) : "f"(v));
    return r;
}
__device__ __forceinline__ void fma2(u64& d, u64 a, u64 b) {
    asm("fma.rn.f32x2 %0, %1, %2, %0;" : "+l"(d) : "l"(a), "l"(b));
}
__device__ __forceinline__ float f32x2_lo(u64 v) {
    float lo;
    asm("{ .reg .f32 hi; mov.b64 {%0, hi}, %1; }" : "=f"(lo) : "l"(v));
    return lo;
}
__device__ __forceinline__ float f32x2_hi(u64 v) {
    float hi;
    asm("{ .reg .f32 lo; mov.b64 {lo, %0}, %1; }" : "=f"(hi) : "l"(v));
    return hi;
}

// ---------------- tf32 helpers (classic warp mma.sync, no tcgen05) ----------------
__device__ __forceinline__ uint32_t cvt_tf32(float f) {
    uint32_t u;
    asm("cvt.rna.tf32.f32 %0, %1;" : "=r"(u) : "f"(f));
    return u;
}
__device__ __forceinline__ void mma_tf32(float* c, const uint32_t* a, const uint32_t* b) {
    asm volatile(
        "mma.sync.aligned.m16n8k8.row.col.f32.tf32.tf32.f32 "
        "{%0,%1,%2,%3}, {%4,%5,%6,%7}, {%8,%9}, {%0,%1,%2,%3};"
        : "+f"(c[0]), "+f"(c[1]), "+f"(c[2]), "+f"(c[3])
        : "r"(a[0]), "r"(a[1]), "r"(a[2]), "r"(a[3]), "r"(b[0]), "r"(b[1]));
}

// ---------------- scratch (static device arrays only) ----------------
__device__ float g_H1  [(size_t)N_NODES * F_HID];
__device__ float g_AGG1[(size_t)N_NODES * F_HID];
__device__ float g_H2  [(size_t)N_NODES * F_PAD];
__device__ int   g_deg [N_NODES];
__device__ float g_dinv[N_NODES];
__device__ int   g_off [N_NODES + 1];
__device__ int   g_cur [N_NODES];
__device__ int   g_bsrc[N_EDGES];
__device__ float g_bnrm[N_EDGES];
__device__ int   g_is64;

// ---------------- 0: zero degrees + detect edge dtype ----------------
__global__ void k_detect_init(const unsigned int* __restrict__ w) {
    int i = blockIdx.x * blockDim.x + threadIdx.x;
    if (i < N_NODES) g_deg[i] = 0;
    if (blockIdx.x == 0) {
        __shared__ int nz;
        if (threadIdx.x == 0) nz = 0;
        __syncthreads();
        if (threadIdx.x < 128 && w[2 * threadIdx.x + 1] != 0u) atomicAdd(&nz, 1);
        __syncthreads();
        if (threadIdx.x == 0) g_is64 = (nz == 0) ? 1 : 0;
    }
}

// ---------------- 1: count in-degrees ----------------
__global__ void k_count(const unsigned int* __restrict__ w) {
    int e = blockIdx.x * blockDim.x + threadIdx.x;
    if (e >= N_EDGES) return;
    int d = g_is64 ? (int)w[2 * ((size_t)N_EDGES + e)] : (int)w[(size_t)N_EDGES + e];
    d = min(max(d, 0), N_NODES - 1);
    atomicAdd(&g_deg[d], 1);
}

// ---------------- 2: prefix scan -> offsets, cursors, dinv ----------------
__global__ void __launch_bounds__(1024) k_scan() {
    __shared__ int sums[1024];
    const int t = threadIdx.x;
    const int CH = (N_NODES + 1023) / 1024;
    int lo = t * CH, hi = min(lo + CH, N_NODES);
    int s = 0;
    for (int i = lo; i < hi; i++) s += g_deg[i];
    sums[t] = s;
    __syncthreads();
    for (int ofs = 1; ofs < 1024; ofs <<= 1) {
        int v = (t >= ofs) ? sums[t - ofs] : 0;
        __syncthreads();
        sums[t] += v;
        __syncthreads();
    }
    int run = (t == 0) ? 0 : sums[t - 1];
    for (int i = lo; i < hi; i++) {
        int d = g_deg[i];
        g_off[i] = run;
        g_cur[i] = run;
        g_dinv[i] = rsqrtf((float)(d + 1));
        run += d;
    }
    if (t == 1023) g_off[N_NODES] = run;
}

// ---------------- 3: GEMM1 via mma.sync tf32 (2-term split, 3 products) ----------
// H1 = X @ W1.  CTA tile 128x128, 8 warps (4 M x 2 N), warp tile 32x64.
// K chunks of 16 (500 -> 512 zero-padded), 2 x k8 mma steps per chunk.
#define G1_KC 16
#define G1_NCHUNK 32

__global__ void __launch_bounds__(256) k_gemm1_mma(const float* __restrict__ X,
                                                   const float* __restrict__ W1) {
    __shared__ float Ah[128][G1_KC + 1];    // 128 x 17
    __shared__ float Al[128][G1_KC + 1];
    __shared__ float Bh[G1_KC][F_HID + 4];  // 16 x 132 (row = 528B, 16B aligned)
    __shared__ float Bl[G1_KC][F_HID + 4];

    const int tid = threadIdx.x;
    const int warp = tid >> 5;
    const int lane = tid & 31;
    const int g = lane >> 2;      // group id 0..7
    const int t4 = lane & 3;      // thread in group 0..3
    const int m0 = (warp & 3) * 32;      // warp M offset in tile
    const int n0w = (warp >> 2) * 64;    // warp N offset
    const int block_row = blockIdx.x * 128;

    float c[2][8][4];
#pragma unroll
    for (int mt = 0; mt < 2; mt++)
#pragma unroll
        for (int nt = 0; nt < 8; nt++)
#pragma unroll
            for (int q = 0; q < 4; q++) c[mt][nt][q] = 0.f;

    for (int ch = 0; ch < G1_NCHUNK; ch++) {
        const int k0 = ch * G1_KC;
        // ---- load + split A tile: 128 rows x 16 k ----
#pragma unroll
        for (int i = 0; i < 2; i++) {
            int idx = tid + 256 * i;          // 0..511
            int row = idx >> 2;               // 0..127
            int c4 = (idx & 3) * 4;           // 0,4,8,12
            int gr = block_row + row, gk = k0 + c4;
            float4 v = make_float4(0.f, 0.f, 0.f, 0.f);
            if (gr < N_NODES && gk + 3 < F_IN)
                v = *reinterpret_cast<const float4*>(X + (size_t)gr * F_IN + gk);
            float vv[4] = {v.x, v.y, v.z, v.w};
#pragma unroll
            for (int j = 0; j < 4; j++) {
                uint32_t hu = cvt_tf32(vv[j]);
                float hf = __uint_as_float(hu);
                uint32_t lu = cvt_tf32(vv[j] - hf);
                Ah[row][c4 + j] = hf;
                Al[row][c4 + j] = __uint_as_float(lu);
            }
        }
        // ---- load + split B tile: 16 k x 128 n ----
#pragma unroll
        for (int i = 0; i < 2; i++) {
            int idx = tid + 256 * i;          // 0..511
            int k = idx >> 5;                 // 0..15
            int n4 = (idx & 31) * 4;          // 0..124
            int gk = k0 + k;
            float4 v = make_float4(0.f, 0.f, 0.f, 0.f);
            if (gk < F_IN)
                v = *reinterpret_cast<const float4*>(W1 + (size_t)gk * F_HID + n4);
            float vv[4] = {v.x, v.y, v.z, v.w};
            float hf[4], lf[4];
#pragma unroll
            for (int j = 0; j < 4; j++) {
                uint32_t hu = cvt_tf32(vv[j]);
                hf[j] = __uint_as_float(hu);
                lf[j] = __uint_as_float(cvt_tf32(vv[j] - hf[j]));
            }
            *reinterpret_cast<float4*>(&Bh[k][n4]) = make_float4(hf[0], hf[1], hf[2], hf[3]);
            *reinterpret_cast<float4*>(&Bl[k][n4]) = make_float4(lf[0], lf[1], lf[2], lf[3]);
        }
        __syncthreads();

#pragma unroll
        for (int ks = 0; ks < G1_KC; ks += 8) {
            // a fragments: 2 M-tiles x (hi,lo), 4 regs each
            uint32_t ah[2][4], al[2][4];
#pragma unroll
            for (int mt = 0; mt < 2; mt++) {
                int bm = m0 + mt * 16;
                ah[mt][0] = __float_as_uint(Ah[bm + g][ks + t4]);
                ah[mt][1] = __float_as_uint(Ah[bm + g + 8][ks + t4]);
                ah[mt][2] = __float_as_uint(Ah[bm + g][ks + t4 + 4]);
                ah[mt][3] = __float_as_uint(Ah[bm + g + 8][ks + t4 + 4]);
                al[mt][0] = __float_as_uint(Al[bm + g][ks + t4]);
                al[mt][1] = __float_as_uint(Al[bm + g + 8][ks + t4]);
                al[mt][2] = __float_as_uint(Al[bm + g][ks + t4 + 4]);
                al[mt][3] = __float_as_uint(Al[bm + g + 8][ks + t4 + 4]);
            }
#pragma unroll
            for (int nt = 0; nt < 8; nt++) {
                int n0 = n0w + nt * 8;
                uint32_t bh[2], bl[2];
                bh[0] = __float_as_uint(Bh[ks + t4][n0 + g]);
                bh[1] = __float_as_uint(Bh[ks + t4 + 4][n0 + g]);
                bl[0] = __float_as_uint(Bl[ks + t4][n0 + g]);
                bl[1] = __float_as_uint(Bl[ks + t4 + 4][n0 + g]);
#pragma unroll
                for (int mt = 0; mt < 2; mt++) {
                    mma_tf32(c[mt][nt], ah[mt], bh);   // hi*hi
                    mma_tf32(c[mt][nt], al[mt], bh);   // lo*hi
                    mma_tf32(c[mt][nt], ah[mt], bl);   // hi*lo
                }
            }
        }
        __syncthreads();
    }

    // ---- epilogue: c-frag (row g / g+8, col 2*t4 / 2*t4+1) ----
#pragma unroll
    for (int mt = 0; mt < 2; mt++) {
#pragma unroll
        for (int nt = 0; nt < 8; nt++) {
            int col = n0w + nt * 8 + t4 * 2;
            int r0 = block_row + m0 + mt * 16 + g;
            if (r0 < N_NODES)
                *reinterpret_cast<float2*>(&g_H1[(size_t)r0 * F_HID + col]) =
                    make_float2(c[mt][nt][0], c[mt][nt][1]);
            int r1 = r0 + 8;
            if (r1 < N_NODES)
                *reinterpret_cast<float2*>(&g_H1[(size_t)r1 * F_HID + col]) =
                    make_float2(c[mt][nt][2], c[mt][nt][3]);
        }
    }
}

// ---------------- 4: bucket edges by dst ----------------
__global__ void k_bucket(const unsigned int* __restrict__ w) {
    int e = blockIdx.x * blockDim.x + threadIdx.x;
    if (e >= N_EDGES) return;
    int s, d;
    if (g_is64) {
        s = (int)w[2 * (size_t)e];
        d = (int)w[2 * ((size_t)N_EDGES + e)];
    } else {
        s = (int)w[e];
        d = (int)w[(size_t)N_EDGES + e];
    }
    s = min(max(s, 0), N_NODES - 1);
    d = min(max(d, 0), N_NODES - 1);
    float nrm = g_dinv[s] * g_dinv[d];
    int pos = atomicAdd(&g_cur[d], 1);
    g_bsrc[pos] = s;
    g_bnrm[pos] = nrm;
}

// ---------------- 5: gather layer1 + bias + relu  (warp per node) ----------------
__global__ void __launch_bounds__(256) k_gather1(const float* __restrict__ b1) {
    int d = blockIdx.x * 8 + (threadIdx.x >> 5);
    if (d >= N_NODES) return;
    int lane = threadIdx.x & 31;
    float di = g_dinv[d];
    float self = di * di;
    const float4 h = *reinterpret_cast<const float4*>(g_H1 + (size_t)d * F_HID + lane * 4);
    float4 acc = make_float4(h.x * self, h.y * self, h.z * self, h.w * self);

    int j = g_off[d], jend = g_off[d + 1];
    for (; j + 1 < jend; j += 2) {
        int s0 = g_bsrc[j], s1 = g_bsrc[j + 1];
        float w0 = g_bnrm[j], w1 = g_bnrm[j + 1];
        float4 v0 = *reinterpret_cast<const float4*>(g_H1 + (size_t)s0 * F_HID + lane * 4);
        float4 v1 = *reinterpret_cast<const float4*>(g_H1 + (size_t)s1 * F_HID + lane * 4);
        acc.x += v0.x * w0 + v1.x * w1;
        acc.y += v0.y * w0 + v1.y * w1;
        acc.z += v0.z * w0 + v1.z * w1;
        acc.w += v0.w * w0 + v1.w * w1;
    }
    if (j < jend) {
        int s0 = g_bsrc[j];
        float w0 = g_bnrm[j];
        float4 v0 = *reinterpret_cast<const float4*>(g_H1 + (size_t)s0 * F_HID + lane * 4);
        acc.x += v0.x * w0; acc.y += v0.y * w0; acc.z += v0.z * w0; acc.w += v0.w * w0;
    }
    float4 bb = *reinterpret_cast<const float4*>(b1 + lane * 4);
    acc.x = fmaxf(acc.x + bb.x, 0.f);
    acc.y = fmaxf(acc.y + bb.y, 0.f);
    acc.z = fmaxf(acc.z + bb.z, 0.f);
    acc.w = fmaxf(acc.w + bb.w, 0.f);
    *reinterpret_cast<float4*>(g_AGG1 + (size_t)d * F_HID + lane * 4) = acc;
}

// ---------------- 6: GEMM2  H2 = AGG1 @ W2  (N=48 padded, packed f32x2) ----------------
__global__ void __launch_bounds__(256) k_gemm2(const float* __restrict__ W2) {
    __shared__ float sIn[32][132];
    __shared__ float sW[128][F_PAD];

    const int block_row = blockIdx.x * 128;
    const int tid = threadIdx.x;
    const int tr = tid >> 4, tc = tid & 15;
    const int r0 = tr * 8, c0 = tc * 3;

    for (int i = tid; i < 128 * F_PAD; i += 256) {
        int k = i / F_PAD, c = i % F_PAD;
        sW[k][c] = (c < F_OUT) ? W2[k * F_OUT + c] : 0.f;
    }

    u64 acc2[4][3];
#pragma unroll
    for (int i = 0; i < 4; i++)
#pragma unroll
        for (int j = 0; j < 3; j++) acc2[i][j] = 0ull;

    for (int k0 = 0; k0 < F_HID; k0 += 32) {
        __syncthreads();
#pragma unroll
        for (int t = 0; t < 4; t++) {
            int idx = tid + 256 * t;
            int r = idx >> 3;
            int kk4 = (idx & 7) * 4;
            int row = block_row + r;
            float4 v = make_float4(0.f, 0.f, 0.f, 0.f);
            if (row < N_NODES)
                v = *reinterpret_cast<const float4*>(&g_AGG1[row * F_HID + k0 + kk4]);
            sIn[kk4 + 0][r] = v.x;
            sIn[kk4 + 1][r] = v.y;
            sIn[kk4 + 2][r] = v.z;
            sIn[kk4 + 3][r] = v.w;
        }
        __syncthreads();

#pragma unroll
        for (int kk = 0; kk < 32; kk++) {
            ulonglong2 ap01 = *reinterpret_cast<const ulonglong2*>(&sIn[kk][r0]);
            ulonglong2 ap23 = *reinterpret_cast<const ulonglong2*>(&sIn[kk][r0 + 4]);
#pragma unroll
            for (int j = 0; j < 3; j++) {
                u64 bd = dup_f32(sW[k0 + kk][c0 + j]);
                fma2(acc2[0][j], ap01.x, bd);
                fma2(acc2[1][j], ap01.y, bd);
                fma2(acc2[2][j], ap23.x, bd);
                fma2(acc2[3][j], ap23.y, bd);
            }
        }
    }

#pragma unroll
    for (int i = 0; i < 8; i++) {
        int r = block_row + r0 + i;
        if (r < N_NODES) {
            int ip = i >> 1;
#pragma unroll
            for (int j = 0; j < 3; j++) {
                float v = (i & 1) ? f32x2_hi(acc2[ip][j]) : f32x2_lo(acc2[ip][j]);
                g_H2[r * F_PAD + c0 + j] = v;
            }
        }
    }
}

// ---------------- 7: gather layer2 + bias + log_softmax -> out ----------------
__global__ void __launch_bounds__(256) k_gather2_out(const float* __restrict__ b2,
                                                     float* __restrict__ out) {
    int d = blockIdx.x * 8 + (threadIdx.x >> 5);
    if (d >= N_NODES) return;
    int lane = threadIdx.x & 31;
    int c1 = lane + 32;
    bool has2 = (c1 < F_OUT);

    float di = g_dinv[d];
    float self = di * di;
    const float* hr = g_H2 + (size_t)d * F_PAD;
    float a0 = hr[lane] * self;
    float a1 = has2 ? hr[c1] * self : 0.f;

    int j = g_off[d], jend = g_off[d + 1];
    for (; j < jend; j++) {
        int s = g_bsrc[j];
        float w = g_bnrm[j];
        const float* sr = g_H2 + (size_t)s * F_PAD;
        a0 += sr[lane] * w;
        if (has2) a1 += sr[c1] * w;
    }

    float z0 = a0 + b2[lane];
    float z1 = has2 ? (a1 + b2[c1]) : -3.0e38f;

    float m = fmaxf(z0, z1);
#pragma unroll
    for (int o = 16; o; o >>= 1) m = fmaxf(m, __shfl_xor_sync(0xffffffffu, m, o));
    float esum = expf(z0 - m) + (has2 ? expf(z1 - m) : 0.f);
#pragma unroll
    for (int o = 16; o; o >>= 1) esum += __shfl_xor_sync(0xffffffffu, esum, o);
    float lse = m + logf(esum);

    out[(size_t)d * F_OUT + lane] = z0 - lse;
    if (has2) out[(size_t)d * F_OUT + c1] = z1 - lse;
}

// ---------------- launch ----------------
extern "C" void kernel_launch(void* const* d_in, const int* in_sizes, int n_in,
                              void* d_out, int out_size) {
    const float* x = 0; const float* W1 = 0; const float* b1 = 0;
    const float* W2 = 0; const float* b2 = 0; const void* ei = 0;
    for (int i = 0; i < n_in; i++) {
        switch (in_sizes[i]) {
            case 25000000: x  = (const float*)d_in[i]; break;
            case 64000:    W1 = (const float*)d_in[i]; break;
            case 128:      b1 = (const float*)d_in[i]; break;
            case 6016:     W2 = (const float*)d_in[i]; break;
            case 47:       b2 = (const float*)d_in[i]; break;
            case 1600000:  ei = d_in[i]; break;
            default: break;
        }
    }
    float* out = (float*)d_out;
    const unsigned int* w = (const unsigned int*)ei;

    k_detect_init<<<(N_NODES + 255) / 256, 256>>>(w);
    k_count      <<<(N_EDGES + 255) / 256, 256>>>(w);
    k_scan       <<<1, 1024>>>();
    k_gemm1_mma  <<<(N_NODES + 127) / 128, 256>>>(x, W1);
    k_bucket     <<<(N_EDGES + 255) / 256, 256>>>(w);
    k_gather1    <<<(N_NODES + 7) / 8, 256>>>(b1);
    k_gemm2      <<<(N_NODES + 127) / 128, 256>>>(W2);
    k_gather2_out<<<(N_NODES + 7) / 8, 256>>>(b2, out);
}

// round 8
// speedup vs baseline: 1.7497x; 1.0383x over previous
#include <cuda_runtime.h>
#include <math.h>
#include <stdint.h>

#define N_NODES 50000
#define N_EDGES 800000
#define F_IN    500
#define F_HID   128
#define F_OUT   47
#define F_PAD   48

typedef unsigned long long u64;

// ---------------- packed f32x2 helpers (Blackwell FFMA2, PTX-only) ----------------
__device__ __forceinline__ u64 dup_f32(float v) {
    u64 r;
    asm("mov.b64 %0, {%1, %1};" : "=l"(r) : "f"(v));
    return r;
}
__device__ __forceinline__ void fma2(u64& d, u64 a, u64 b) {
    asm("fma.rn.f32x2 %0, %1, %2, %0;" : "+l"(d) : "l"(a), "l"(b));
}
__device__ __forceinline__ float f32x2_lo(u64 v) {
    float lo;
    asm("{ .reg .f32 hi; mov.b64 {%0, hi}, %1; }" : "=f"(lo) : "l"(v));
    return lo;
}
__device__ __forceinline__ float f32x2_hi(u64 v) {
    float hi;
    asm("{ .reg .f32 lo; mov.b64 {lo, %0}, %1; }" : "=f"(hi) : "l"(v));
    return hi;
}

// ---------------- tf32 helpers (classic warp mma.sync) ----------------
__device__ __forceinline__ uint32_t cvt_tf32(float f) {
    uint32_t u;
    asm("cvt.rna.tf32.f32 %0, %1;" : "=r"(u) : "f"(f));
    return u;
}
__device__ __forceinline__ void mma_tf32(float* c, const uint32_t* a, const uint32_t* b) {
    asm volatile(
        "mma.sync.aligned.m16n8k8.row.col.f32.tf32.tf32.f32 "
        "{%0,%1,%2,%3}, {%4,%5,%6,%7}, {%8,%9}, {%0,%1,%2,%3};"
        : "+f"(c[0]), "+f"(c[1]), "+f"(c[2]), "+f"(c[3])
        : "r"(a[0]), "r"(a[1]), "r"(a[2]), "r"(a[3]), "r"(b[0]), "r"(b[1]));
}

// ---------------- scratch (static device arrays only) ----------------
__device__ float g_H1  [(size_t)N_NODES * F_HID];
__device__ float g_AGG1[(size_t)N_NODES * F_HID];
__device__ float g_H2  [(size_t)N_NODES * F_PAD];
__device__ int   g_deg [N_NODES];
__device__ float g_dinv[N_NODES];
__device__ int   g_off [N_NODES + 1];
__device__ int   g_cur [N_NODES];
__device__ int   g_bsrc[N_EDGES];
__device__ float g_bnrm[N_EDGES];
__device__ int   g_is64;

// ---------------- 0: zero degrees + detect edge dtype ----------------
__global__ void k_detect_init(const unsigned int* __restrict__ w) {
    int i = blockIdx.x * blockDim.x + threadIdx.x;
    if (i < N_NODES) g_deg[i] = 0;
    if (blockIdx.x == 0) {
        __shared__ int nz;
        if (threadIdx.x == 0) nz = 0;
        __syncthreads();
        if (threadIdx.x < 128 && w[2 * threadIdx.x + 1] != 0u) atomicAdd(&nz, 1);
        __syncthreads();
        if (threadIdx.x == 0) g_is64 = (nz == 0) ? 1 : 0;
    }
}

// ---------------- 1: count in-degrees ----------------
__global__ void k_count(const unsigned int* __restrict__ w) {
    int e = blockIdx.x * blockDim.x + threadIdx.x;
    if (e >= N_EDGES) return;
    int d = g_is64 ? (int)w[2 * ((size_t)N_EDGES + e)] : (int)w[(size_t)N_EDGES + e];
    d = min(max(d, 0), N_NODES - 1);
    atomicAdd(&g_deg[d], 1);
}

// ---------------- 2: prefix scan -> offsets, cursors, dinv ----------------
__global__ void __launch_bounds__(1024) k_scan() {
    __shared__ int sums[1024];
    const int t = threadIdx.x;
    const int CH = (N_NODES + 1023) / 1024;
    int lo = t * CH, hi = min(lo + CH, N_NODES);
    int s = 0;
    for (int i = lo; i < hi; i++) s += g_deg[i];
    sums[t] = s;
    __syncthreads();
    for (int ofs = 1; ofs < 1024; ofs <<= 1) {
        int v = (t >= ofs) ? sums[t - ofs] : 0;
        __syncthreads();
        sums[t] += v;
        __syncthreads();
    }
    int run = (t == 0) ? 0 : sums[t - 1];
    for (int i = lo; i < hi; i++) {
        int d = g_deg[i];
        g_off[i] = run;
        g_cur[i] = run;
        g_dinv[i] = rsqrtf((float)(d + 1));
        run += d;
    }
    if (t == 1023) g_off[N_NODES] = run;
}

// ---------------- 3: GEMM1 via mma.sync tf32, 2-term split, packed A hi/lo -------
// H1 = X @ W1.  CTA tile 128x128, 8 warps (4 M x 2 N), warp tile 32x64.
// K chunks of 16 (500 -> 512 zero-padded), 2 x k8 mma steps per chunk.
// A smem: [k][row] float2 (hi,lo) -> 1 LDS.64 per fragment reg pair.
// B smem: [k][n] float (hi only; a_hi*b_lo term dropped, err ~1e-4 << 1e-3).
#define G1_KC 16
#define G1_NCHUNK 32

__global__ void __launch_bounds__(256) k_gemm1_mma(const float* __restrict__ X,
                                                   const float* __restrict__ W1) {
    __shared__ float2 As2[G1_KC][132];     // [k][row+pad] (hi,lo)
    __shared__ float  Bh [G1_KC][132];     // [k][n+pad]  hi only

    const int tid = threadIdx.x;
    const int warp = tid >> 5;
    const int lane = tid & 31;
    const int g = lane >> 2;      // group id 0..7
    const int t4 = lane & 3;      // thread in group 0..3
    const int m0 = (warp & 3) * 32;      // warp M offset in tile
    const int n0w = (warp >> 2) * 64;    // warp N offset
    const int block_row = blockIdx.x * 128;

    float c[2][8][4];
#pragma unroll
    for (int mt = 0; mt < 2; mt++)
#pragma unroll
        for (int nt = 0; nt < 8; nt++)
#pragma unroll
            for (int q = 0; q < 4; q++) c[mt][nt][q] = 0.f;

    for (int ch = 0; ch < G1_NCHUNK; ch++) {
        const int k0 = ch * G1_KC;
        // ---- load + split A tile: 128 rows x 16 k -> As2[k][row] = (hi,lo) ----
#pragma unroll
        for (int i = 0; i < 2; i++) {
            int idx = tid + 256 * i;          // 0..511
            int row = idx >> 2;               // 0..127
            int c4 = (idx & 3) * 4;           // 0,4,8,12
            int gr = block_row + row, gk = k0 + c4;
            float4 v = make_float4(0.f, 0.f, 0.f, 0.f);
            if (gr < N_NODES && gk + 3 < F_IN)
                v = *reinterpret_cast<const float4*>(X + (size_t)gr * F_IN + gk);
            float vv[4] = {v.x, v.y, v.z, v.w};
#pragma unroll
            for (int j = 0; j < 4; j++) {
                float hf = __uint_as_float(cvt_tf32(vv[j]));
                float lf = __uint_as_float(cvt_tf32(vv[j] - hf));
                As2[c4 + j][row] = make_float2(hf, lf);
            }
        }
        // ---- load B tile: 16 k x 128 n -> Bh[k][n] (hi only) ----
#pragma unroll
        for (int i = 0; i < 2; i++) {
            int idx = tid + 256 * i;          // 0..511
            int k = idx >> 5;                 // 0..15
            int n4 = (idx & 31) * 4;          // 0..124
            int gk = k0 + k;
            float4 v = make_float4(0.f, 0.f, 0.f, 0.f);
            if (gk < F_IN)
                v = *reinterpret_cast<const float4*>(W1 + (size_t)gk * F_HID + n4);
            float vv[4] = {v.x, v.y, v.z, v.w};
            float hf[4];
#pragma unroll
            for (int j = 0; j < 4; j++)
                hf[j] = __uint_as_float(cvt_tf32(vv[j]));
            *reinterpret_cast<float4*>(&Bh[k][n4]) = make_float4(hf[0], hf[1], hf[2], hf[3]);
        }
        __syncthreads();

#pragma unroll
        for (int ks = 0; ks < G1_KC; ks += 8) {
            // a fragments: 2 M-tiles x (hi,lo) via packed float2 loads
            uint32_t ah[2][4], al[2][4];
#pragma unroll
            for (int mt = 0; mt < 2; mt++) {
                int bm = m0 + mt * 16;
                float2 p0 = As2[ks + t4][bm + g];
                float2 p1 = As2[ks + t4][bm + g + 8];
                float2 p2 = As2[ks + t4 + 4][bm + g];
                float2 p3 = As2[ks + t4 + 4][bm + g + 8];
                ah[mt][0] = __float_as_uint(p0.x); al[mt][0] = __float_as_uint(p0.y);
                ah[mt][1] = __float_as_uint(p1.x); al[mt][1] = __float_as_uint(p1.y);
                ah[mt][2] = __float_as_uint(p2.x); al[mt][2] = __float_as_uint(p2.y);
                ah[mt][3] = __float_as_uint(p3.x); al[mt][3] = __float_as_uint(p3.y);
            }
#pragma unroll
            for (int nt = 0; nt < 8; nt++) {
                int n0 = n0w + nt * 8;
                uint32_t bh[2];
                bh[0] = __float_as_uint(Bh[ks + t4][n0 + g]);
                bh[1] = __float_as_uint(Bh[ks + t4 + 4][n0 + g]);
#pragma unroll
                for (int mt = 0; mt < 2; mt++) {
                    mma_tf32(c[mt][nt], ah[mt], bh);   // hi*hi
                    mma_tf32(c[mt][nt], al[mt], bh);   // lo*hi
                }
            }
        }
        __syncthreads();
    }

    // ---- epilogue: c-frag (row g / g+8, col 2*t4 / 2*t4+1) ----
#pragma unroll
    for (int mt = 0; mt < 2; mt++) {
#pragma unroll
        for (int nt = 0; nt < 8; nt++) {
            int col = n0w + nt * 8 + t4 * 2;
            int r0 = block_row + m0 + mt * 16 + g;
            if (r0 < N_NODES)
                *reinterpret_cast<float2*>(&g_H1[(size_t)r0 * F_HID + col]) =
                    make_float2(c[mt][nt][0], c[mt][nt][1]);
            int r1 = r0 + 8;
            if (r1 < N_NODES)
                *reinterpret_cast<float2*>(&g_H1[(size_t)r1 * F_HID + col]) =
                    make_float2(c[mt][nt][2], c[mt][nt][3]);
        }
    }
}

// ---------------- 4: bucket edges by dst ----------------
__global__ void k_bucket(const unsigned int* __restrict__ w) {
    int e = blockIdx.x * blockDim.x + threadIdx.x;
    if (e >= N_EDGES) return;
    int s, d;
    if (g_is64) {
        s = (int)w[2 * (size_t)e];
        d = (int)w[2 * ((size_t)N_EDGES + e)];
    } else {
        s = (int)w[e];
        d = (int)w[(size_t)N_EDGES + e];
    }
    s = min(max(s, 0), N_NODES - 1);
    d = min(max(d, 0), N_NODES - 1);
    float nrm = g_dinv[s] * g_dinv[d];
    int pos = atomicAdd(&g_cur[d], 1);
    g_bsrc[pos] = s;
    g_bnrm[pos] = nrm;
}

// ---------------- 5: gather layer1 + bias + relu  (warp per node) ----------------
__global__ void __launch_bounds__(256) k_gather1(const float* __restrict__ b1) {
    int d = blockIdx.x * 8 + (threadIdx.x >> 5);
    if (d >= N_NODES) return;
    int lane = threadIdx.x & 31;
    float di = g_dinv[d];
    float self = di * di;
    const float4 h = *reinterpret_cast<const float4*>(g_H1 + (size_t)d * F_HID + lane * 4);
    float4 acc = make_float4(h.x * self, h.y * self, h.z * self, h.w * self);

    int j = g_off[d], jend = g_off[d + 1];
    for (; j + 1 < jend; j += 2) {
        int s0 = g_bsrc[j], s1 = g_bsrc[j + 1];
        float w0 = g_bnrm[j], w1 = g_bnrm[j + 1];
        float4 v0 = *reinterpret_cast<const float4*>(g_H1 + (size_t)s0 * F_HID + lane * 4);
        float4 v1 = *reinterpret_cast<const float4*>(g_H1 + (size_t)s1 * F_HID + lane * 4);
        acc.x += v0.x * w0 + v1.x * w1;
        acc.y += v0.y * w0 + v1.y * w1;
        acc.z += v0.z * w0 + v1.z * w1;
        acc.w += v0.w * w0 + v1.w * w1;
    }
    if (j < jend) {
        int s0 = g_bsrc[j];
        float w0 = g_bnrm[j];
        float4 v0 = *reinterpret_cast<const float4*>(g_H1 + (size_t)s0 * F_HID + lane * 4);
        acc.x += v0.x * w0; acc.y += v0.y * w0; acc.z += v0.z * w0; acc.w += v0.w * w0;
    }
    float4 bb = *reinterpret_cast<const float4*>(b1 + lane * 4);
    acc.x = fmaxf(acc.x + bb.x, 0.f);
    acc.y = fmaxf(acc.y + bb.y, 0.f);
    acc.z = fmaxf(acc.z + bb.z, 0.f);
    acc.w = fmaxf(acc.w + bb.w, 0.f);
    *reinterpret_cast<float4*>(g_AGG1 + (size_t)d * F_HID + lane * 4) = acc;
}

// ---------------- 6: GEMM2  H2 = AGG1 @ W2  (N=48 padded, packed f32x2) ----------------
__global__ void __launch_bounds__(256) k_gemm2(const float* __restrict__ W2) {
    __shared__ float sIn[32][132];
    __shared__ float sW[128][F_PAD];

    const int block_row = blockIdx.x * 128;
    const int tid = threadIdx.x;
    const int tr = tid >> 4, tc = tid & 15;
    const int r0 = tr * 8, c0 = tc * 3;

    for (int i = tid; i < 128 * F_PAD; i += 256) {
        int k = i / F_PAD, c = i % F_PAD;
        sW[k][c] = (c < F_OUT) ? W2[k * F_OUT + c] : 0.f;
    }

    u64 acc2[4][3];
#pragma unroll
    for (int i = 0; i < 4; i++)
#pragma unroll
        for (int j = 0; j < 3; j++) acc2[i][j] = 0ull;

    for (int k0 = 0; k0 < F_HID; k0 += 32) {
        __syncthreads();
#pragma unroll
        for (int t = 0; t < 4; t++) {
            int idx = tid + 256 * t;
            int r = idx >> 3;
            int kk4 = (idx & 7) * 4;
            int row = block_row + r;
            float4 v = make_float4(0.f, 0.f, 0.f, 0.f);
            if (row < N_NODES)
                v = *reinterpret_cast<const float4*>(&g_AGG1[row * F_HID + k0 + kk4]);
            sIn[kk4 + 0][r] = v.x;
            sIn[kk4 + 1][r] = v.y;
            sIn[kk4 + 2][r] = v.z;
            sIn[kk4 + 3][r] = v.w;
        }
        __syncthreads();

#pragma unroll
        for (int kk = 0; kk < 32; kk++) {
            ulonglong2 ap01 = *reinterpret_cast<const ulonglong2*>(&sIn[kk][r0]);
            ulonglong2 ap23 = *reinterpret_cast<const ulonglong2*>(&sIn[kk][r0 + 4]);
#pragma unroll
            for (int j = 0; j < 3; j++) {
                u64 bd = dup_f32(sW[k0 + kk][c0 + j]);
                fma2(acc2[0][j], ap01.x, bd);
                fma2(acc2[1][j], ap01.y, bd);
                fma2(acc2[2][j], ap23.x, bd);
                fma2(acc2[3][j], ap23.y, bd);
            }
        }
    }

#pragma unroll
    for (int i = 0; i < 8; i++) {
        int r = block_row + r0 + i;
        if (r < N_NODES) {
            int ip = i >> 1;
#pragma unroll
            for (int j = 0; j < 3; j++) {
                float v = (i & 1) ? f32x2_hi(acc2[ip][j]) : f32x2_lo(acc2[ip][j]);
                g_H2[r * F_PAD + c0 + j] = v;
            }
        }
    }
}

// ---------------- 7: gather layer2 + bias + log_softmax -> out ----------------
__global__ void __launch_bounds__(256) k_gather2_out(const float* __restrict__ b2,
                                                     float* __restrict__ out) {
    int d = blockIdx.x * 8 + (threadIdx.x >> 5);
    if (d >= N_NODES) return;
    int lane = threadIdx.x & 31;
    int c1 = lane + 32;
    bool has2 = (c1 < F_OUT);

    float di = g_dinv[d];
    float self = di * di;
    const float* hr = g_H2 + (size_t)d * F_PAD;
    float a0 = hr[lane] * self;
    float a1 = has2 ? hr[c1] * self : 0.f;

    int j = g_off[d], jend = g_off[d + 1];
    for (; j < jend; j++) {
        int s = g_bsrc[j];
        float w = g_bnrm[j];
        const float* sr = g_H2 + (size_t)s * F_PAD;
        a0 += sr[lane] * w;
        if (has2) a1 += sr[c1] * w;
    }

    float z0 = a0 + b2[lane];
    float z1 = has2 ? (a1 + b2[c1]) : -3.0e38f;

    float m = fmaxf(z0, z1);
#pragma unroll
    for (int o = 16; o; o >>= 1) m = fmaxf(m, __shfl_xor_sync(0xffffffffu, m, o));
    float esum = expf(z0 - m) + (has2 ? expf(z1 - m) : 0.f);
#pragma unroll
    for (int o = 16; o; o >>= 1) esum += __shfl_xor_sync(0xffffffffu, esum, o);
    float lse = m + logf(esum);

    out[(size_t)d * F_OUT + lane] = z0 - lse;
    if (has2) out[(size_t)d * F_OUT + c1] = z1 - lse;
}

// ---------------- launch ----------------
extern "C" void kernel_launch(void* const* d_in, const int* in_sizes, int n_in,
                              void* d_out, int out_size) {
    const float* x = 0; const float* W1 = 0; const float* b1 = 0;
    const float* W2 = 0; const float* b2 = 0; const void* ei = 0;
    for (int i = 0; i < n_in; i++) {
        switch (in_sizes[i]) {
            case 25000000: x  = (const float*)d_in[i]; break;
            case 64000:    W1 = (const float*)d_in[i]; break;
            case 128:      b1 = (const float*)d_in[i]; break;
            case 6016:     W2 = (const float*)d_in[i]; break;
            case 47:       b2 = (const float*)d_in[i]; break;
            case 1600000:  ei = d_in[i]; break;
            default: break;
        }
    }
    float* out = (float*)d_out;
    const unsigned int* w = (const unsigned int*)ei;

    k_detect_init<<<(N_NODES + 255) / 256, 256>>>(w);
    k_count      <<<(N_EDGES + 255) / 256, 256>>>(w);
    k_scan       <<<1, 1024>>>();
    k_gemm1_mma  <<<(N_NODES + 127) / 128, 256>>>(x, W1);
    k_bucket     <<<(N_EDGES + 255) / 256, 256>>>(w);
    k_gather1    <<<(N_NODES + 7) / 8, 256>>>(b1);
    k_gemm2      <<<(N_NODES + 127) / 128, 256>>>(W2);
    k_gather2_out<<<(N_NODES + 7) / 8, 256>>>(b2, out);
}